// round 4
// baseline (speedup 1.0000x reference)
#include <cuda_runtime.h>
#include <cstdint>

#define NN 10000
#define EE 160000
#define CC 128
#define DD 512
#define HH 64
#define W4C 640
#define HT 130   // padded stride for transposed h tiles [k][e], 128 edges + 2 pad

#define NCHUNK 5
#define ECHUNK (EE / NCHUNK)          // 32000 edges per chunk

#define INV_SQRT3 0.57735026918962576f
#define INV_SQRT2 0.70710678118654752f
#define LIN_SCALE 0.088388347648318447f   // 1/sqrt(128)

// Scratch (device globals: no runtime allocation allowed)
__device__ float g_w[(size_t)EE * W4C];    // radial weights [E,640]
__device__ float g_agg[(size_t)NN * DD];   // segment-sum accumulator

typedef unsigned long long u64;

__device__ __forceinline__ u64 pack2(float lo, float hi) {
    u64 r; asm("mov.b64 %0, {%1, %2};" : "=l"(r) : "f"(lo), "f"(hi)); return r;
}
__device__ __forceinline__ void unpack2(u64 v, float& lo, float& hi) {
    asm("mov.b64 {%0, %1}, %2;" : "=f"(lo), "=f"(hi) : "l"(v));
}
__device__ __forceinline__ void fma2(u64& d, u64 a, u64 b) {
    asm("fma.rn.f32x2 %0, %1, %2, %0;" : "+l"(d) : "l"(a), "l"(b));
}
__device__ __forceinline__ float silu_f(float x) { return x / (1.0f + __expf(-x)); }

// ---------------------------------------------------------------------------
// One 64->64 layer, register-blocked: 4 columns x 8 edges per thread.
// ---------------------------------------------------------------------------
__device__ __forceinline__ void layer_rb(const float* __restrict__ W,
                                         const float* sIn, float* sOut,
                                         int jbase, int ebase)
{
    u64 acc[4][4];
#pragma unroll
    for (int c = 0; c < 4; ++c)
#pragma unroll
        for (int p = 0; p < 4; ++p) acc[c][p] = 0ull;

#pragma unroll 4
    for (int k = 0; k < HH; ++k) {
        const float4 w4 = __ldg((const float4*)(W + k * HH + jbase));
        const u64* hp = (const u64*)(sIn + k * HT + ebase);
        const u64 h0 = hp[0], h1 = hp[1], h2 = hp[2], h3 = hp[3];
        const float wv[4] = {w4.x, w4.y, w4.z, w4.w};
#pragma unroll
        for (int c = 0; c < 4; ++c) {
            const u64 w2 = pack2(wv[c], wv[c]);
            fma2(acc[c][0], h0, w2);
            fma2(acc[c][1], h1, w2);
            fma2(acc[c][2], h2, w2);
            fma2(acc[c][3], h3, w2);
        }
    }
#pragma unroll
    for (int c = 0; c < 4; ++c) {
        u64* op = (u64*)(sOut + (jbase + c) * HT + ebase);
#pragma unroll
        for (int p = 0; p < 4; ++p) {
            float lo, hi; unpack2(acc[c][p], lo, hi);
            op[p] = pack2(silu_f(lo), silu_f(hi));
        }
    }
}

// One 64-column pass of [128e,64] @ [64,640], stores float4 rows to g_w.
__device__ __forceinline__ void gemm4_pass(const float* __restrict__ Wm4,
                                           const float* sIn,
                                           int col0, int jbase, int ebase, size_t e0)
{
    u64 acc[4][4];
#pragma unroll
    for (int c = 0; c < 4; ++c)
#pragma unroll
        for (int p = 0; p < 4; ++p) acc[c][p] = 0ull;

#pragma unroll 4
    for (int k = 0; k < HH; ++k) {
        const float4 w4 = __ldg((const float4*)(Wm4 + k * W4C + col0 + jbase));
        const u64* hp = (const u64*)(sIn + k * HT + ebase);
        const u64 h0 = hp[0], h1 = hp[1], h2 = hp[2], h3 = hp[3];
        const float wv[4] = {w4.x, w4.y, w4.z, w4.w};
#pragma unroll
        for (int c = 0; c < 4; ++c) {
            const u64 w2 = pack2(wv[c], wv[c]);
            fma2(acc[c][0], h0, w2);
            fma2(acc[c][1], h1, w2);
            fma2(acc[c][2], h2, w2);
            fma2(acc[c][3], h3, w2);
        }
    }
#pragma unroll
    for (int p = 0; p < 4; ++p) {
        float v0[4], v1[4];
#pragma unroll
        for (int c = 0; c < 4; ++c) unpack2(acc[c][p], v0[c], v1[c]);
        float* d0 = g_w + (e0 + (size_t)(ebase + 2 * p)) * W4C + col0 + jbase;
        float* d1 = d0 + W4C;
        *(float4*)d0 = make_float4(v0[0], v0[1], v0[2], v0[3]);
        *(float4*)d1 = make_float4(v1[0], v1[1], v1[2], v1[3]);
    }
}

// ---------------------------------------------------------------------------
// Kernel 1: full radial MLP for 128 edges per block (chunked by eoff).
// ---------------------------------------------------------------------------
__global__ void __launch_bounds__(256, 3)
mlp_kernel(const float* __restrict__ emb, const float* __restrict__ Wm1,
           const float* __restrict__ Wm2, const float* __restrict__ Wm3,
           const float* __restrict__ Wm4, int eoff)
{
    extern __shared__ float sm[];
    float* sE  = sm;            // 128 edges x 8
    float* sW1 = sm + 1024;     // 8 x 64
    float* sHa = sm + 1536;     // [64][130]
    float* sHb = sm + 1536 + HH * HT;

    const int tid = threadIdx.x;
    const size_t e0 = (size_t)eoff + (size_t)blockIdx.x * 128;

    for (int i = tid; i < 1024; i += 256) sE[i] = emb[e0 * 8 + i];
    for (int i = tid; i < 512; i += 256)  sW1[i] = Wm1[i];
    __syncthreads();

    const int jq = tid & 15;
    const int eg = tid >> 4;
    const int jbase = jq * 4;
    const int ebase = eg * 8;

    // layer 1: [128,8] @ [8,64] -> silu -> transposed sHa
    {
        float w[8][4];
#pragma unroll
        for (int r = 0; r < 8; ++r) {
            const float4 w4 = *(const float4*)(sW1 + r * HH + jbase);
            w[r][0] = w4.x; w[r][1] = w4.y; w[r][2] = w4.z; w[r][3] = w4.w;
        }
#pragma unroll
        for (int e = 0; e < 8; ++e) {
            const float4 ea = *(const float4*)(sE + (ebase + e) * 8);
            const float4 eb = *(const float4*)(sE + (ebase + e) * 8 + 4);
            const float er[8] = {ea.x, ea.y, ea.z, ea.w, eb.x, eb.y, eb.z, eb.w};
#pragma unroll
            for (int c = 0; c < 4; ++c) {
                float acc = 0.f;
#pragma unroll
                for (int r = 0; r < 8; ++r) acc += er[r] * w[r][c];
                sHa[(jbase + c) * HT + ebase + e] = silu_f(acc);
            }
        }
    }
    __syncthreads();
    layer_rb(Wm2, sHa, sHb, jbase, ebase);
    __syncthreads();
    layer_rb(Wm3, sHb, sHa, jbase, ebase);
    __syncthreads();

#pragma unroll 1
    for (int pass = 0; pass < 10; ++pass)
        gemm4_pass(Wm4, sHa, pass * 64, jbase, ebase, e0);
}

// ---------------------------------------------------------------------------
// Kernel 2: zero the aggregation buffer (float4)
// ---------------------------------------------------------------------------
__global__ void __launch_bounds__(256)
zero_kernel()
{
    const size_t i = (size_t)blockIdx.x * 256 + threadIdx.x;
    ((float4*)g_agg)[i] = make_float4(0.f, 0.f, 0.f, 0.f);
}

// ---------------------------------------------------------------------------
// Kernel 3: per-edge tensor-product messages + vector red scatter (chunked).
// ---------------------------------------------------------------------------
__global__ void __launch_bounds__(256)
msg_kernel(const float* __restrict__ nf, const float* __restrict__ ef,
           const float* __restrict__ attrs,
           const int* __restrict__ snd, const int* __restrict__ rcv, int eoff)
{
    const size_t e = (size_t)eoff + (size_t)((blockIdx.x * 256 + threadIdx.x) >> 5);
    const int lane = threadIdx.x & 31;

    const int s = snd[e], r = rcv[e];
    const float4 sh = *(const float4*)(attrs + e * 4);
    const float sh0 = sh.x, s1x = sh.y, s1y = sh.z, s1z = sh.w;

    const float* ps = nf + (size_t)s * DD;
    const float* pr = nf + (size_t)r * DD;
    const float* pe = ef + e * DD;
    const int c0 = lane * 4;

    float x0[4];
    {
        float4 a = *(const float4*)(ps + c0);
        float4 b = *(const float4*)(pr + c0);
        float4 c = *(const float4*)(pe + c0);
        x0[0] = a.x + b.x + c.x; x0[1] = a.y + b.y + c.y;
        x0[2] = a.z + b.z + c.z; x0[3] = a.w + b.w + c.w;
    }
    float xv[12];
#pragma unroll
    for (int q = 0; q < 3; ++q) {
        const int off = CC + 3 * c0 + 4 * q;
        float4 a = *(const float4*)(ps + off);
        float4 b = *(const float4*)(pr + off);
        float4 c = *(const float4*)(pe + off);
        xv[4 * q + 0] = a.x + b.x + c.x; xv[4 * q + 1] = a.y + b.y + c.y;
        xv[4 * q + 2] = a.z + b.z + c.z; xv[4 * q + 3] = a.w + b.w + c.w;
    }

    const float* pw = g_w + e * W4C + c0;
    float w0[4], w1[4], w2[4], w3[4], w4[4];
    { float4 v = *(const float4*)(pw      ); w0[0]=v.x; w0[1]=v.y; w0[2]=v.z; w0[3]=v.w; }
    { float4 v = *(const float4*)(pw + 128); w1[0]=v.x; w1[1]=v.y; w1[2]=v.z; w1[3]=v.w; }
    { float4 v = *(const float4*)(pw + 256); w2[0]=v.x; w2[1]=v.y; w2[2]=v.z; w2[3]=v.w; }
    { float4 v = *(const float4*)(pw + 384); w3[0]=v.x; w3[1]=v.y; w3[2]=v.z; w3[3]=v.w; }
    { float4 v = *(const float4*)(pw + 512); w4[0]=v.x; w4[1]=v.y; w4[2]=v.z; w4[3]=v.w; }

    float m0v[4], m1v[12];
#pragma unroll
    for (int cc = 0; cc < 4; ++cc) {
        const float u0 = xv[3 * cc], u1 = xv[3 * cc + 1], u2 = xv[3 * cc + 2];
        const float dot = u0 * s1x + u1 * s1y + u2 * s1z;
        m0v[cc] = w0[cc] * x0[cc] * sh0 + w1[cc] * dot * INV_SQRT3;
        const float cx = u1 * s1z - u2 * s1y;
        const float cy = u2 * s1x - u0 * s1z;
        const float cz = u0 * s1y - u1 * s1x;
        m1v[3 * cc + 0] = w2[cc] * u0 * sh0 + w3[cc] * x0[cc] * s1x + w4[cc] * cx * INV_SQRT2;
        m1v[3 * cc + 1] = w2[cc] * u1 * sh0 + w3[cc] * x0[cc] * s1y + w4[cc] * cy * INV_SQRT2;
        m1v[3 * cc + 2] = w2[cc] * u2 * sh0 + w3[cc] * x0[cc] * s1z + w4[cc] * cz * INV_SQRT2;
    }

    float* pagg = g_agg + (size_t)r * DD;
    asm volatile("red.global.add.v4.f32 [%0], {%1,%2,%3,%4};"
                 :: "l"(pagg + c0), "f"(m0v[0]), "f"(m0v[1]), "f"(m0v[2]), "f"(m0v[3])
                 : "memory");
    float* pv = pagg + CC + 3 * c0;
    asm volatile("red.global.add.v4.f32 [%0], {%1,%2,%3,%4};"
                 :: "l"(pv), "f"(m1v[0]), "f"(m1v[1]), "f"(m1v[2]), "f"(m1v[3])
                 : "memory");
    asm volatile("red.global.add.v4.f32 [%0], {%1,%2,%3,%4};"
                 :: "l"(pv + 4), "f"(m1v[4]), "f"(m1v[5]), "f"(m1v[6]), "f"(m1v[7])
                 : "memory");
    asm volatile("red.global.add.v4.f32 [%0], {%1,%2,%3,%4};"
                 :: "l"(pv + 8), "f"(m1v[8]), "f"(m1v[9]), "f"(m1v[10]), "f"(m1v[11])
                 : "memory");
}

// ---------------------------------------------------------------------------
// Kernel 4: out = agg + eq_linear(agg,res) + eq_linear(nf,skip).
// ---------------------------------------------------------------------------
#define OST 18
#define OARR (CC * OST)

__global__ void __launch_bounds__(256, 2)
out_kernel(const float* __restrict__ nf,
           const float* __restrict__ rW0, const float* __restrict__ rW1,
           const float* __restrict__ skW0, const float* __restrict__ skW1,
           float* __restrict__ out)
{
    extern __shared__ float osm[];
    float* sA0 = osm;
    float* sN0 = osm + 4 * OARR;

    const int tid = threadIdx.x;
    const size_t n0 = (size_t)blockIdx.x * 16;

    for (int i = tid; i < 16 * DD; i += 256) {
        const int n = i >> 9;
        const int q = i & 511;
        const float va = g_agg[(n0 + n) * DD + q];
        const float vb = nf[(n0 + n) * DD + q];
        if (q < CC) {
            sA0[q * OST + n] = va;
            sN0[q * OST + n] = vb;
        } else {
            const int rr = q - CC;
            const int c = rr / 3;
            const int ax = rr - 3 * c;
            sA0[(1 + ax) * OARR + c * OST + n] = va;
            sN0[(1 + ax) * OARR + c * OST + n] = vb;
        }
    }
    __syncthreads();

    const int dg = tid & 31;
    const int ng = tid >> 5;
    const int d0 = dg * 4;
    const int nn2 = ng * 2;

    u64 acc0[4], accx[4], accy[4], accz[4];
#pragma unroll
    for (int d = 0; d < 4; ++d) { acc0[d] = 0ull; accx[d] = 0ull; accy[d] = 0ull; accz[d] = 0ull; }

#pragma unroll 4
    for (int c = 0; c < CC; ++c) {
        const float4 wr0 = __ldg((const float4*)(rW0  + c * CC + d0));
        const float4 ws0 = __ldg((const float4*)(skW0 + c * CC + d0));
        const float4 wr1 = __ldg((const float4*)(rW1  + c * CC + d0));
        const float4 ws1 = __ldg((const float4*)(skW1 + c * CC + d0));
        const int ab = c * OST + nn2;
        const u64 pA0 = *(const u64*)(sA0 + ab);
        const u64 pAx = *(const u64*)(sA0 + OARR + ab);
        const u64 pAy = *(const u64*)(sA0 + 2 * OARR + ab);
        const u64 pAz = *(const u64*)(sA0 + 3 * OARR + ab);
        const u64 pN0 = *(const u64*)(sN0 + ab);
        const u64 pNx = *(const u64*)(sN0 + OARR + ab);
        const u64 pNy = *(const u64*)(sN0 + 2 * OARR + ab);
        const u64 pNz = *(const u64*)(sN0 + 3 * OARR + ab);

        const float r0a[4] = {wr0.x, wr0.y, wr0.z, wr0.w};
        const float s0a[4] = {ws0.x, ws0.y, ws0.z, ws0.w};
        const float r1a[4] = {wr1.x, wr1.y, wr1.z, wr1.w};
        const float s1a[4] = {ws1.x, ws1.y, ws1.z, ws1.w};
#pragma unroll
        for (int d = 0; d < 4; ++d) {
            const u64 pr0 = pack2(r0a[d], r0a[d]);
            const u64 ps0 = pack2(s0a[d], s0a[d]);
            const u64 pr1 = pack2(r1a[d], r1a[d]);
            const u64 ps1 = pack2(s1a[d], s1a[d]);
            fma2(acc0[d], pA0, pr0); fma2(acc0[d], pN0, ps0);
            fma2(accx[d], pAx, pr1); fma2(accx[d], pNx, ps1);
            fma2(accy[d], pAy, pr1); fma2(accy[d], pNy, ps1);
            fma2(accz[d], pAz, pr1); fma2(accz[d], pNz, ps1);
        }
    }

#pragma unroll
    for (int s = 0; s < 2; ++s) {
        const int n = nn2 + s;
        const size_t ob = (n0 + n) * DD;
        float o4[4], vv[12];
#pragma unroll
        for (int d = 0; d < 4; ++d) {
            float lo, hi, v;
            unpack2(acc0[d], lo, hi); v = s ? hi : lo;
            o4[d] = sA0[(d0 + d) * OST + n] + v * LIN_SCALE;
            unpack2(accx[d], lo, hi); v = s ? hi : lo;
            vv[3 * d + 0] = sA0[OARR + (d0 + d) * OST + n] + v * LIN_SCALE;
            unpack2(accy[d], lo, hi); v = s ? hi : lo;
            vv[3 * d + 1] = sA0[2 * OARR + (d0 + d) * OST + n] + v * LIN_SCALE;
            unpack2(accz[d], lo, hi); v = s ? hi : lo;
            vv[3 * d + 2] = sA0[3 * OARR + (d0 + d) * OST + n] + v * LIN_SCALE;
        }
        *(float4*)(out + ob + d0) = make_float4(o4[0], o4[1], o4[2], o4[3]);
        float* vb = out + ob + CC + 3 * d0;
        *(float4*)(vb    ) = make_float4(vv[0], vv[1], vv[2],  vv[3]);
        *(float4*)(vb + 4) = make_float4(vv[4], vv[5], vv[6],  vv[7]);
        *(float4*)(vb + 8) = make_float4(vv[8], vv[9], vv[10], vv[11]);
    }
}

// ---------------------------------------------------------------------------
extern "C" void kernel_launch(void* const* d_in, const int* in_sizes, int n_in,
                              void* d_out, int out_size)
{
    const float* nf    = (const float*)d_in[0];
    const float* ef    = (const float*)d_in[1];
    const float* attrs = (const float*)d_in[2];
    const float* emb   = (const float*)d_in[3];
    const int*   snd   = (const int*)d_in[4];
    const int*   rcv   = (const int*)d_in[5];
    const float* Wm1   = (const float*)d_in[6];
    const float* Wm2   = (const float*)d_in[7];
    const float* Wm3   = (const float*)d_in[8];
    const float* Wm4   = (const float*)d_in[9];
    const float* rW0   = (const float*)d_in[10];
    const float* rW1   = (const float*)d_in[11];
    const float* sW0   = (const float*)d_in[12];
    const float* sW1   = (const float*)d_in[13];
    float* out = (float*)d_out;

    const int mlp_smem = (1536 + 2 * HH * HT) * 4;   // 72704 B
    const int out_smem = 8 * OARR * 4;               // 73728 B

    static cudaStream_t s2;
    static cudaEvent_t evFork, evJoin, evChunk[NCHUNK];
    static bool init_done = false;
    if (!init_done) {
        cudaFuncSetAttribute(mlp_kernel, cudaFuncAttributeMaxDynamicSharedMemorySize, mlp_smem);
        cudaFuncSetAttribute(out_kernel, cudaFuncAttributeMaxDynamicSharedMemorySize, out_smem);
        cudaStreamCreateWithFlags(&s2, cudaStreamNonBlocking);
        cudaEventCreateWithFlags(&evFork, cudaEventDisableTiming);
        cudaEventCreateWithFlags(&evJoin, cudaEventDisableTiming);
        for (int q = 0; q < NCHUNK; ++q)
            cudaEventCreateWithFlags(&evChunk[q], cudaEventDisableTiming);
        init_done = true;
    }

    // fork side stream from the capture-origin (default) stream
    cudaEventRecord(evFork, 0);
    cudaStreamWaitEvent(s2, evFork, 0);

    // zero runs on s2, parallel with mlp chunk 0
    zero_kernel<<<(NN * DD) / (256 * 4), 256, 0, s2>>>();

    for (int q = 0; q < NCHUNK; ++q) {
        mlp_kernel<<<ECHUNK / 128, 256, mlp_smem>>>(emb, Wm1, Wm2, Wm3, Wm4, q * ECHUNK);
        cudaEventRecord(evChunk[q], 0);
        cudaStreamWaitEvent(s2, evChunk[q], 0);
        msg_kernel<<<ECHUNK * 32 / 256, 256, 0, s2>>>(nf, ef, attrs, snd, rcv, q * ECHUNK);
    }

    // join back to the default stream
    cudaEventRecord(evJoin, s2);
    cudaStreamWaitEvent(0, evJoin, 0);

    out_kernel<<<NN / 16, 256, out_smem>>>(nf, rW0, rW1, sW0, sW1, out);
}

// round 5
// speedup vs baseline: 1.6315x; 1.6315x over previous
#include <cuda_runtime.h>
#include <cuda_bf16.h>
#include <cstdint>

#define NN 10000
#define EE 160000
#define CC 128
#define DD 512
#define HH 64
#define W4C 640
#define HT 130   // padded stride for transposed h tiles [k][e]

#define INV_SQRT3 0.57735026918962576f
#define INV_SQRT2 0.70710678118654752f
#define LIN_SCALE 0.088388347648318447f   // 1/sqrt(128)

// Scratch (device globals: no runtime allocation allowed)
__device__ float g_w[(size_t)EE * W4C];     // radial weights [E,640]
__device__ float g_agg[(size_t)NN * DD];    // segment-sum accumulator
// Wm4 split into bf16 hi/lo, packed in m16n8k16 B-fragment order:
// [kt(4)][nt(80)][lane(32)][reg(2)] as u32 (bf16x2)
__device__ uint32_t g_b4h[4 * 80 * 32 * 2];
__device__ uint32_t g_b4l[4 * 80 * 32 * 2];

typedef unsigned long long u64;

__device__ __forceinline__ u64 pack2(float lo, float hi) {
    u64 r; asm("mov.b64 %0, {%1, %2};" : "=l"(r) : "f"(lo), "f"(hi)); return r;
}
__device__ __forceinline__ void unpack2(u64 v, float& lo, float& hi) {
    asm("mov.b64 {%0, %1}, %2;" : "=f"(lo), "=f"(hi) : "l"(v));
}
__device__ __forceinline__ void fma2(u64& d, u64 a, u64 b) {
    asm("fma.rn.f32x2 %0, %1, %2, %0;" : "+l"(d) : "l"(a), "l"(b));
}
__device__ __forceinline__ float silu_f(float x) { return x / (1.0f + __expf(-x)); }

// pack two bf16 (first -> low half) into u32
__device__ __forceinline__ uint32_t pack_bf16(__nv_bfloat16 first, __nv_bfloat16 second) {
    return (uint32_t)__bfloat16_as_ushort(first) | ((uint32_t)__bfloat16_as_ushort(second) << 16);
}
// split pair (x = first/low element, y = second/high) into hi/lo bf16x2 regs
__device__ __forceinline__ void split_pack(float x, float y, uint32_t& hi, uint32_t& lo) {
    const __nv_bfloat16 bx = __float2bfloat16(x);
    const __nv_bfloat16 by = __float2bfloat16(y);
    const __nv_bfloat16 rx = __float2bfloat16(x - __bfloat162float(bx));
    const __nv_bfloat16 ry = __float2bfloat16(y - __bfloat162float(by));
    hi = pack_bf16(bx, by);
    lo = pack_bf16(rx, ry);
}

__device__ __forceinline__ void mma_bf16(float* c, const uint32_t* a, uint32_t b0, uint32_t b1) {
    asm volatile("mma.sync.aligned.m16n8k16.row.col.f32.bf16.bf16.f32 "
        "{%0,%1,%2,%3}, {%4,%5,%6,%7}, {%8,%9}, {%0,%1,%2,%3};"
        : "+f"(c[0]), "+f"(c[1]), "+f"(c[2]), "+f"(c[3])
        : "r"(a[0]), "r"(a[1]), "r"(a[2]), "r"(a[3]), "r"(b0), "r"(b1));
}

// ---------------------------------------------------------------------------
// prep: split Wm4 -> bf16 hi/lo in B-fragment order. 10240 threads.
// ---------------------------------------------------------------------------
__global__ void __launch_bounds__(256)
prep_b4_kernel(const float* __restrict__ Wm4)
{
    const int tid = blockIdx.x * 256 + threadIdx.x;
    if (tid >= 4 * 80 * 32) return;
    const int lane = tid & 31;
    const int idx = tid >> 5;           // kt*80 + nt
    const int kt = idx / 80, nt = idx % 80;
    const int g = lane >> 2, t = lane & 3;
    const int n = nt * 8 + g;
    const int k0 = kt * 16 + 2 * t;

    const float v00 = Wm4[(k0)     * W4C + n];
    const float v01 = Wm4[(k0 + 1) * W4C + n];
    const float v10 = Wm4[(k0 + 8) * W4C + n];
    const float v11 = Wm4[(k0 + 9) * W4C + n];
    uint32_t h0, l0, h1, l1;
    split_pack(v00, v01, h0, l0);
    split_pack(v10, v11, h1, l1);
    const int base = (idx * 32 + lane) * 2;
    g_b4h[base]     = h0;
    g_b4h[base + 1] = h1;
    g_b4l[base]     = l0;
    g_b4l[base + 1] = l1;
}

// ---------------------------------------------------------------------------
// One 64->64 layer, register-blocked: 4 columns x 8 edges per thread.
// ---------------------------------------------------------------------------
__device__ __forceinline__ void layer_rb(const float* __restrict__ W,
                                         const float* sIn, float* sOut,
                                         int jbase, int ebase)
{
    u64 acc[4][4];
#pragma unroll
    for (int c = 0; c < 4; ++c)
#pragma unroll
        for (int p = 0; p < 4; ++p) acc[c][p] = 0ull;

#pragma unroll 4
    for (int k = 0; k < HH; ++k) {
        const float4 w4 = __ldg((const float4*)(W + k * HH + jbase));
        const u64* hp = (const u64*)(sIn + k * HT + ebase);
        const u64 h0 = hp[0], h1 = hp[1], h2 = hp[2], h3 = hp[3];
        const float wv[4] = {w4.x, w4.y, w4.z, w4.w};
#pragma unroll
        for (int c = 0; c < 4; ++c) {
            const u64 w2 = pack2(wv[c], wv[c]);
            fma2(acc[c][0], h0, w2);
            fma2(acc[c][1], h1, w2);
            fma2(acc[c][2], h2, w2);
            fma2(acc[c][3], h3, w2);
        }
    }
#pragma unroll
    for (int c = 0; c < 4; ++c) {
        u64* op = (u64*)(sOut + (jbase + c) * HT + ebase);
#pragma unroll
        for (int p = 0; p < 4; ++p) {
            float lo, hi; unpack2(acc[c][p], lo, hi);
            op[p] = pack2(silu_f(lo), silu_f(hi));
        }
    }
}

// ---------------------------------------------------------------------------
// Kernel 1: radial MLP. Layers 1-3 scalar; GEMM4 via mma.sync bf16 3-term.
// 128 edges per block, 256 threads (8 warps x 16 edges).
// ---------------------------------------------------------------------------
__global__ void __launch_bounds__(256, 2)
mlp_kernel(const float* __restrict__ emb, const float* __restrict__ Wm1,
           const float* __restrict__ Wm2, const float* __restrict__ Wm3)
{
    extern __shared__ float sm[];
    float* sE  = sm;            // 128 x 8
    float* sW1 = sm + 1024;     // 8 x 64
    float* sHa = sm + 1536;     // [64][130]
    float* sHb = sm + 1536 + HH * HT;

    const int tid = threadIdx.x;
    const size_t e0 = (size_t)blockIdx.x * 128;

    for (int i = tid; i < 1024; i += 256) sE[i] = emb[e0 * 8 + i];
    for (int i = tid; i < 512; i += 256)  sW1[i] = Wm1[i];
    __syncthreads();

    const int jq = tid & 15;
    const int eg = tid >> 4;
    const int jbase = jq * 4;
    const int ebase = eg * 8;

    // layer 1
    {
        float w[8][4];
#pragma unroll
        for (int r = 0; r < 8; ++r) {
            const float4 w4 = *(const float4*)(sW1 + r * HH + jbase);
            w[r][0] = w4.x; w[r][1] = w4.y; w[r][2] = w4.z; w[r][3] = w4.w;
        }
#pragma unroll
        for (int e = 0; e < 8; ++e) {
            const float4 ea = *(const float4*)(sE + (ebase + e) * 8);
            const float4 eb = *(const float4*)(sE + (ebase + e) * 8 + 4);
            const float er[8] = {ea.x, ea.y, ea.z, ea.w, eb.x, eb.y, eb.z, eb.w};
#pragma unroll
            for (int c = 0; c < 4; ++c) {
                float acc = 0.f;
#pragma unroll
                for (int r = 0; r < 8; ++r) acc += er[r] * w[r][c];
                sHa[(jbase + c) * HT + ebase + e] = silu_f(acc);
            }
        }
    }
    __syncthreads();
    layer_rb(Wm2, sHa, sHb, jbase, ebase);
    __syncthreads();
    layer_rb(Wm3, sHb, sHa, jbase, ebase);
    __syncthreads();

    // ---- GEMM4: [128,64] @ [64,640] via m16n8k16 bf16, 3-term split ----
    const int w    = tid >> 5;
    const int lane = tid & 31;
    const int g = lane >> 2, t = lane & 3;
    const int er = w * 16 + g;       // rows er / er+8 of this block's 128 edges

    // A fragments (pass-invariant): Ah/Al[kt][0..3]
    uint32_t Ah[4][4], Al[4][4];
#pragma unroll
    for (int kt = 0; kt < 4; ++kt) {
        const int k0 = kt * 16 + 2 * t;
        const float* b0 = sHa + (k0)     * HT;
        const float* b1 = sHa + (k0 + 1) * HT;
        const float* b8 = sHa + (k0 + 8) * HT;
        const float* b9 = sHa + (k0 + 9) * HT;
        split_pack(b0[er],     b1[er],     Ah[kt][0], Al[kt][0]);
        split_pack(b0[er + 8], b1[er + 8], Ah[kt][1], Al[kt][1]);
        split_pack(b8[er],     b9[er],     Ah[kt][2], Al[kt][2]);
        split_pack(b8[er + 8], b9[er + 8], Ah[kt][3], Al[kt][3]);
    }

    float* wrow0 = g_w + (e0 + er)     * W4C + 2 * t;
    float* wrow8 = g_w + (e0 + er + 8) * W4C + 2 * t;

#pragma unroll 1
    for (int np = 0; np < 40; ++np) {          // 80 n-tiles, 2 at a time
        const int nt0 = np * 2, nt1 = nt0 + 1;
        float acc0[4] = {0.f, 0.f, 0.f, 0.f};
        float acc1[4] = {0.f, 0.f, 0.f, 0.f};
#pragma unroll
        for (int kt = 0; kt < 4; ++kt) {
            const int i0 = ((kt * 80 + nt0) * 32 + lane) * 2;
            const int i1 = ((kt * 80 + nt1) * 32 + lane) * 2;
            const uint2 bh0 = *(const uint2*)(g_b4h + i0);
            const uint2 bh1 = *(const uint2*)(g_b4h + i1);
            const uint2 bl0 = *(const uint2*)(g_b4l + i0);
            const uint2 bl1 = *(const uint2*)(g_b4l + i1);
            mma_bf16(acc0, Ah[kt], bh0.x, bh0.y);
            mma_bf16(acc1, Ah[kt], bh1.x, bh1.y);
            mma_bf16(acc0, Al[kt], bh0.x, bh0.y);
            mma_bf16(acc1, Al[kt], bh1.x, bh1.y);
            mma_bf16(acc0, Ah[kt], bl0.x, bl0.y);
            mma_bf16(acc1, Ah[kt], bl1.x, bl1.y);
        }
        const int c0 = nt0 * 8;
        const int c1 = nt1 * 8;
        *(float2*)(wrow0 + c0) = make_float2(acc0[0], acc0[1]);
        *(float2*)(wrow8 + c0) = make_float2(acc0[2], acc0[3]);
        *(float2*)(wrow0 + c1) = make_float2(acc1[0], acc1[1]);
        *(float2*)(wrow8 + c1) = make_float2(acc1[2], acc1[3]);
    }
}

// ---------------------------------------------------------------------------
// Kernel 2: zero the aggregation buffer (float4)
// ---------------------------------------------------------------------------
__global__ void __launch_bounds__(256)
zero_kernel()
{
    const size_t i = (size_t)blockIdx.x * 256 + threadIdx.x;
    ((float4*)g_agg)[i] = make_float4(0.f, 0.f, 0.f, 0.f);
}

// ---------------------------------------------------------------------------
// Kernel 3: per-edge tensor-product messages + vector red scatter.
// ---------------------------------------------------------------------------
__global__ void __launch_bounds__(256)
msg_kernel(const float* __restrict__ nf, const float* __restrict__ ef,
           const float* __restrict__ attrs,
           const int* __restrict__ snd, const int* __restrict__ rcv)
{
    const size_t e = (size_t)((blockIdx.x * 256 + threadIdx.x) >> 5);
    const int lane = threadIdx.x & 31;

    const int s = snd[e], r = rcv[e];
    const float4 sh = *(const float4*)(attrs + e * 4);
    const float sh0 = sh.x, s1x = sh.y, s1y = sh.z, s1z = sh.w;

    const float* ps = nf + (size_t)s * DD;
    const float* pr = nf + (size_t)r * DD;
    const float* pe = ef + e * DD;
    const int c0 = lane * 4;

    float x0[4];
    {
        float4 a = *(const float4*)(ps + c0);
        float4 b = *(const float4*)(pr + c0);
        float4 c = *(const float4*)(pe + c0);
        x0[0] = a.x + b.x + c.x; x0[1] = a.y + b.y + c.y;
        x0[2] = a.z + b.z + c.z; x0[3] = a.w + b.w + c.w;
    }
    float xv[12];
#pragma unroll
    for (int q = 0; q < 3; ++q) {
        const int off = CC + 3 * c0 + 4 * q;
        float4 a = *(const float4*)(ps + off);
        float4 b = *(const float4*)(pr + off);
        float4 c = *(const float4*)(pe + off);
        xv[4 * q + 0] = a.x + b.x + c.x; xv[4 * q + 1] = a.y + b.y + c.y;
        xv[4 * q + 2] = a.z + b.z + c.z; xv[4 * q + 3] = a.w + b.w + c.w;
    }

    const float* pw = g_w + e * W4C + c0;
    float w0[4], w1[4], w2[4], w3[4], w4[4];
    { float4 v = *(const float4*)(pw      ); w0[0]=v.x; w0[1]=v.y; w0[2]=v.z; w0[3]=v.w; }
    { float4 v = *(const float4*)(pw + 128); w1[0]=v.x; w1[1]=v.y; w1[2]=v.z; w1[3]=v.w; }
    { float4 v = *(const float4*)(pw + 256); w2[0]=v.x; w2[1]=v.y; w2[2]=v.z; w2[3]=v.w; }
    { float4 v = *(const float4*)(pw + 384); w3[0]=v.x; w3[1]=v.y; w3[2]=v.z; w3[3]=v.w; }
    { float4 v = *(const float4*)(pw + 512); w4[0]=v.x; w4[1]=v.y; w4[2]=v.z; w4[3]=v.w; }

    float m0v[4], m1v[12];
#pragma unroll
    for (int cc = 0; cc < 4; ++cc) {
        const float u0 = xv[3 * cc], u1 = xv[3 * cc + 1], u2 = xv[3 * cc + 2];
        const float dot = u0 * s1x + u1 * s1y + u2 * s1z;
        m0v[cc] = w0[cc] * x0[cc] * sh0 + w1[cc] * dot * INV_SQRT3;
        const float cx = u1 * s1z - u2 * s1y;
        const float cy = u2 * s1x - u0 * s1z;
        const float cz = u0 * s1y - u1 * s1x;
        m1v[3 * cc + 0] = w2[cc] * u0 * sh0 + w3[cc] * x0[cc] * s1x + w4[cc] * cx * INV_SQRT2;
        m1v[3 * cc + 1] = w2[cc] * u1 * sh0 + w3[cc] * x0[cc] * s1y + w4[cc] * cy * INV_SQRT2;
        m1v[3 * cc + 2] = w2[cc] * u2 * sh0 + w3[cc] * x0[cc] * s1z + w4[cc] * cz * INV_SQRT2;
    }

    float* pagg = g_agg + (size_t)r * DD;
    asm volatile("red.global.add.v4.f32 [%0], {%1,%2,%3,%4};"
                 :: "l"(pagg + c0), "f"(m0v[0]), "f"(m0v[1]), "f"(m0v[2]), "f"(m0v[3])
                 : "memory");
    float* pv = pagg + CC + 3 * c0;
    asm volatile("red.global.add.v4.f32 [%0], {%1,%2,%3,%4};"
                 :: "l"(pv), "f"(m1v[0]), "f"(m1v[1]), "f"(m1v[2]), "f"(m1v[3])
                 : "memory");
    asm volatile("red.global.add.v4.f32 [%0], {%1,%2,%3,%4};"
                 :: "l"(pv + 4), "f"(m1v[4]), "f"(m1v[5]), "f"(m1v[6]), "f"(m1v[7])
                 : "memory");
    asm volatile("red.global.add.v4.f32 [%0], {%1,%2,%3,%4};"
                 :: "l"(pv + 8), "f"(m1v[8]), "f"(m1v[9]), "f"(m1v[10]), "f"(m1v[11])
                 : "memory");
}

// ---------------------------------------------------------------------------
// Kernel 4: out = agg + eq_linear(agg,res) + eq_linear(nf,skip).
// ---------------------------------------------------------------------------
#define OST 18
#define OARR (CC * OST)

__global__ void __launch_bounds__(256, 2)
out_kernel(const float* __restrict__ nf,
           const float* __restrict__ rW0, const float* __restrict__ rW1,
           const float* __restrict__ skW0, const float* __restrict__ skW1,
           float* __restrict__ out)
{
    extern __shared__ float osm[];
    float* sA0 = osm;
    float* sN0 = osm + 4 * OARR;

    const int tid = threadIdx.x;
    const size_t n0 = (size_t)blockIdx.x * 16;

    for (int i = tid; i < 16 * DD; i += 256) {
        const int n = i >> 9;
        const int q = i & 511;
        const float va = g_agg[(n0 + n) * DD + q];
        const float vb = nf[(n0 + n) * DD + q];
        if (q < CC) {
            sA0[q * OST + n] = va;
            sN0[q * OST + n] = vb;
        } else {
            const int rr = q - CC;
            const int c = rr / 3;
            const int ax = rr - 3 * c;
            sA0[(1 + ax) * OARR + c * OST + n] = va;
            sN0[(1 + ax) * OARR + c * OST + n] = vb;
        }
    }
    __syncthreads();

    const int dg = tid & 31;
    const int ng = tid >> 5;
    const int d0 = dg * 4;
    const int nn2 = ng * 2;

    u64 acc0[4], accx[4], accy[4], accz[4];
#pragma unroll
    for (int d = 0; d < 4; ++d) { acc0[d] = 0ull; accx[d] = 0ull; accy[d] = 0ull; accz[d] = 0ull; }

#pragma unroll 4
    for (int c = 0; c < CC; ++c) {
        const float4 wr0 = __ldg((const float4*)(rW0  + c * CC + d0));
        const float4 ws0 = __ldg((const float4*)(skW0 + c * CC + d0));
        const float4 wr1 = __ldg((const float4*)(rW1  + c * CC + d0));
        const float4 ws1 = __ldg((const float4*)(skW1 + c * CC + d0));
        const int ab = c * OST + nn2;
        const u64 pA0 = *(const u64*)(sA0 + ab);
        const u64 pAx = *(const u64*)(sA0 + OARR + ab);
        const u64 pAy = *(const u64*)(sA0 + 2 * OARR + ab);
        const u64 pAz = *(const u64*)(sA0 + 3 * OARR + ab);
        const u64 pN0 = *(const u64*)(sN0 + ab);
        const u64 pNx = *(const u64*)(sN0 + OARR + ab);
        const u64 pNy = *(const u64*)(sN0 + 2 * OARR + ab);
        const u64 pNz = *(const u64*)(sN0 + 3 * OARR + ab);

        const float r0a[4] = {wr0.x, wr0.y, wr0.z, wr0.w};
        const float s0a[4] = {ws0.x, ws0.y, ws0.z, ws0.w};
        const float r1a[4] = {wr1.x, wr1.y, wr1.z, wr1.w};
        const float s1a[4] = {ws1.x, ws1.y, ws1.z, ws1.w};
#pragma unroll
        for (int d = 0; d < 4; ++d) {
            const u64 pr0 = pack2(r0a[d], r0a[d]);
            const u64 ps0 = pack2(s0a[d], s0a[d]);
            const u64 pr1 = pack2(r1a[d], r1a[d]);
            const u64 ps1 = pack2(s1a[d], s1a[d]);
            fma2(acc0[d], pA0, pr0); fma2(acc0[d], pN0, ps0);
            fma2(accx[d], pAx, pr1); fma2(accx[d], pNx, ps1);
            fma2(accy[d], pAy, pr1); fma2(accy[d], pNy, ps1);
            fma2(accz[d], pAz, pr1); fma2(accz[d], pNz, ps1);
        }
    }

#pragma unroll
    for (int s = 0; s < 2; ++s) {
        const int n = nn2 + s;
        const size_t ob = (n0 + n) * DD;
        float o4[4], vv[12];
#pragma unroll
        for (int d = 0; d < 4; ++d) {
            float lo, hi, v;
            unpack2(acc0[d], lo, hi); v = s ? hi : lo;
            o4[d] = sA0[(d0 + d) * OST + n] + v * LIN_SCALE;
            unpack2(accx[d], lo, hi); v = s ? hi : lo;
            vv[3 * d + 0] = sA0[OARR + (d0 + d) * OST + n] + v * LIN_SCALE;
            unpack2(accy[d], lo, hi); v = s ? hi : lo;
            vv[3 * d + 1] = sA0[2 * OARR + (d0 + d) * OST + n] + v * LIN_SCALE;
            unpack2(accz[d], lo, hi); v = s ? hi : lo;
            vv[3 * d + 2] = sA0[3 * OARR + (d0 + d) * OST + n] + v * LIN_SCALE;
        }
        *(float4*)(out + ob + d0) = make_float4(o4[0], o4[1], o4[2], o4[3]);
        float* vb = out + ob + CC + 3 * d0;
        *(float4*)(vb    ) = make_float4(vv[0], vv[1], vv[2],  vv[3]);
        *(float4*)(vb + 4) = make_float4(vv[4], vv[5], vv[6],  vv[7]);
        *(float4*)(vb + 8) = make_float4(vv[8], vv[9], vv[10], vv[11]);
    }
}

// ---------------------------------------------------------------------------
extern "C" void kernel_launch(void* const* d_in, const int* in_sizes, int n_in,
                              void* d_out, int out_size)
{
    const float* nf    = (const float*)d_in[0];
    const float* ef    = (const float*)d_in[1];
    const float* attrs = (const float*)d_in[2];
    const float* emb   = (const float*)d_in[3];
    const int*   snd   = (const int*)d_in[4];
    const int*   rcv   = (const int*)d_in[5];
    const float* Wm1   = (const float*)d_in[6];
    const float* Wm2   = (const float*)d_in[7];
    const float* Wm3   = (const float*)d_in[8];
    const float* Wm4   = (const float*)d_in[9];
    const float* rW0   = (const float*)d_in[10];
    const float* rW1   = (const float*)d_in[11];
    const float* sW0   = (const float*)d_in[12];
    const float* sW1   = (const float*)d_in[13];
    float* out = (float*)d_out;

    const int mlp_smem = (1536 + 2 * HH * HT) * 4;   // 72704 B
    const int out_smem = 8 * OARR * 4;               // 73728 B
    static bool attr_done = false;
    if (!attr_done) {
        cudaFuncSetAttribute(mlp_kernel, cudaFuncAttributeMaxDynamicSharedMemorySize, mlp_smem);
        cudaFuncSetAttribute(out_kernel, cudaFuncAttributeMaxDynamicSharedMemorySize, out_smem);
        attr_done = true;
    }

    zero_kernel<<<(NN * DD) / (256 * 4), 256>>>();
    prep_b4_kernel<<<(4 * 80 * 32 + 255) / 256, 256>>>(Wm4);
    mlp_kernel<<<EE / 128, 256, mlp_smem>>>(emb, Wm1, Wm2, Wm3);
    msg_kernel<<<EE / 8, 256>>>(nf, ef, attrs, snd, rcv);
    out_kernel<<<NN / 16, 256, out_smem>>>(nf, rW0, rW1, sW0, sW1, out);
}

// round 6
// speedup vs baseline: 1.9761x; 1.2112x over previous
#include <cuda_runtime.h>
#include <cuda_bf16.h>
#include <cstdint>

#define NN 10000
#define EE 160000
#define CC 128
#define DD 512
#define HH 64
#define W4C 640
#define HT 130   // padded stride for transposed h tiles [k][e]

#define INV_SQRT3 0.57735026918962576f
#define INV_SQRT2 0.70710678118654752f
#define LIN_SCALE 0.088388347648318447f   // 1/sqrt(128)

// Scratch (device globals: no runtime allocation allowed)
__device__ float g_agg[(size_t)NN * DD];          // segment-sum accumulator
// A fragments (layer-3 activations), bf16 hi/lo, m16n8k16 A-fragment order:
// uint4 per [blk(1250)][warp(8)][kt(4)][lane(32)]
__device__ uint4 g_ah4[1250 * 8 * 4 * 32];
__device__ uint4 g_al4[1250 * 8 * 4 * 32];
// Wm4 split into bf16 hi/lo, packed in m16n8k16 B-fragment order:
// [kt(4)][nt(80)][lane(32)][reg(2)] as u32 (bf16x2)
__device__ uint32_t g_b4h[4 * 80 * 32 * 2];
__device__ uint32_t g_b4l[4 * 80 * 32 * 2];

typedef unsigned long long u64;

__device__ __forceinline__ u64 pack2(float lo, float hi) {
    u64 r; asm("mov.b64 %0, {%1, %2};" : "=l"(r) : "f"(lo), "f"(hi)); return r;
}
__device__ __forceinline__ void unpack2(u64 v, float& lo, float& hi) {
    asm("mov.b64 {%0, %1}, %2;" : "=f"(lo), "=f"(hi) : "l"(v));
}
__device__ __forceinline__ void fma2(u64& d, u64 a, u64 b) {
    asm("fma.rn.f32x2 %0, %1, %2, %0;" : "+l"(d) : "l"(a), "l"(b));
}
__device__ __forceinline__ float silu_f(float x) { return x / (1.0f + __expf(-x)); }

__device__ __forceinline__ uint32_t pack_bf16(__nv_bfloat16 first, __nv_bfloat16 second) {
    return (uint32_t)__bfloat16_as_ushort(first) | ((uint32_t)__bfloat16_as_ushort(second) << 16);
}
__device__ __forceinline__ void split_pack(float x, float y, uint32_t& hi, uint32_t& lo) {
    const __nv_bfloat16 bx = __float2bfloat16(x);
    const __nv_bfloat16 by = __float2bfloat16(y);
    const __nv_bfloat16 rx = __float2bfloat16(x - __bfloat162float(bx));
    const __nv_bfloat16 ry = __float2bfloat16(y - __bfloat162float(by));
    hi = pack_bf16(bx, by);
    lo = pack_bf16(rx, ry);
}

__device__ __forceinline__ void mma_bf16(float* c, const uint32_t* a, uint32_t b0, uint32_t b1) {
    asm volatile("mma.sync.aligned.m16n8k16.row.col.f32.bf16.bf16.f32 "
        "{%0,%1,%2,%3}, {%4,%5,%6,%7}, {%8,%9}, {%0,%1,%2,%3};"
        : "+f"(c[0]), "+f"(c[1]), "+f"(c[2]), "+f"(c[3])
        : "r"(a[0]), "r"(a[1]), "r"(a[2]), "r"(a[3]), "r"(b0), "r"(b1));
}

// ---------------------------------------------------------------------------
// prep: split Wm4 -> bf16 hi/lo in B-fragment order.
// ---------------------------------------------------------------------------
__global__ void __launch_bounds__(256)
prep_b4_kernel(const float* __restrict__ Wm4)
{
    const int tid = blockIdx.x * 256 + threadIdx.x;
    if (tid >= 4 * 80 * 32) return;
    const int lane = tid & 31;
    const int idx = tid >> 5;           // kt*80 + nt
    const int kt = idx / 80, nt = idx % 80;
    const int g = lane >> 2, t = lane & 3;
    const int n = nt * 8 + g;
    const int k0 = kt * 16 + 2 * t;

    const float v00 = Wm4[(k0)     * W4C + n];
    const float v01 = Wm4[(k0 + 1) * W4C + n];
    const float v10 = Wm4[(k0 + 8) * W4C + n];
    const float v11 = Wm4[(k0 + 9) * W4C + n];
    uint32_t h0, l0, h1, l1;
    split_pack(v00, v01, h0, l0);
    split_pack(v10, v11, h1, l1);
    const int base = (idx * 32 + lane) * 2;
    g_b4h[base]     = h0;
    g_b4h[base + 1] = h1;
    g_b4l[base]     = l0;
    g_b4l[base + 1] = l1;
}

// ---------------------------------------------------------------------------
// One 64->64 layer, register-blocked: 4 columns x 8 edges per thread.
// ---------------------------------------------------------------------------
__device__ __forceinline__ void layer_rb(const float* __restrict__ W,
                                         const float* sIn, float* sOut,
                                         int jbase, int ebase)
{
    u64 acc[4][4];
#pragma unroll
    for (int c = 0; c < 4; ++c)
#pragma unroll
        for (int p = 0; p < 4; ++p) acc[c][p] = 0ull;

#pragma unroll 4
    for (int k = 0; k < HH; ++k) {
        const float4 w4 = __ldg((const float4*)(W + k * HH + jbase));
        const u64* hp = (const u64*)(sIn + k * HT + ebase);
        const u64 h0 = hp[0], h1 = hp[1], h2 = hp[2], h3 = hp[3];
        const float wv[4] = {w4.x, w4.y, w4.z, w4.w};
#pragma unroll
        for (int c = 0; c < 4; ++c) {
            const u64 w2 = pack2(wv[c], wv[c]);
            fma2(acc[c][0], h0, w2);
            fma2(acc[c][1], h1, w2);
            fma2(acc[c][2], h2, w2);
            fma2(acc[c][3], h3, w2);
        }
    }
#pragma unroll
    for (int c = 0; c < 4; ++c) {
        u64* op = (u64*)(sOut + (jbase + c) * HT + ebase);
#pragma unroll
        for (int p = 0; p < 4; ++p) {
            float lo, hi; unpack2(acc[c][p], lo, hi);
            op[p] = pack2(silu_f(lo), silu_f(hi));
        }
    }
}

// ---------------------------------------------------------------------------
// Kernel 1: MLP layers 1-3 (scalar) -> store split bf16 A-fragments.
// 128 edges per block, 256 threads.
// ---------------------------------------------------------------------------
__global__ void __launch_bounds__(256, 2)
mlp_kernel(const float* __restrict__ emb, const float* __restrict__ Wm1,
           const float* __restrict__ Wm2, const float* __restrict__ Wm3)
{
    extern __shared__ float sm[];
    float* sE  = sm;            // 128 x 8
    float* sW1 = sm + 1024;     // 8 x 64
    float* sHa = sm + 1536;     // [64][130]
    float* sHb = sm + 1536 + HH * HT;

    const int tid = threadIdx.x;
    const size_t e0 = (size_t)blockIdx.x * 128;

    for (int i = tid; i < 1024; i += 256) sE[i] = emb[e0 * 8 + i];
    for (int i = tid; i < 512; i += 256)  sW1[i] = Wm1[i];
    __syncthreads();

    const int jq = tid & 15;
    const int eg = tid >> 4;
    const int jbase = jq * 4;
    const int ebase = eg * 8;

    // layer 1
    {
        float w[8][4];
#pragma unroll
        for (int r = 0; r < 8; ++r) {
            const float4 w4 = *(const float4*)(sW1 + r * HH + jbase);
            w[r][0] = w4.x; w[r][1] = w4.y; w[r][2] = w4.z; w[r][3] = w4.w;
        }
#pragma unroll
        for (int e = 0; e < 8; ++e) {
            const float4 ea = *(const float4*)(sE + (ebase + e) * 8);
            const float4 eb = *(const float4*)(sE + (ebase + e) * 8 + 4);
            const float er[8] = {ea.x, ea.y, ea.z, ea.w, eb.x, eb.y, eb.z, eb.w};
#pragma unroll
            for (int c = 0; c < 4; ++c) {
                float acc = 0.f;
#pragma unroll
                for (int r = 0; r < 8; ++r) acc += er[r] * w[r][c];
                sHa[(jbase + c) * HT + ebase + e] = silu_f(acc);
            }
        }
    }
    __syncthreads();
    layer_rb(Wm2, sHa, sHb, jbase, ebase);
    __syncthreads();
    layer_rb(Wm3, sHb, sHa, jbase, ebase);
    __syncthreads();

    // build + store A fragments (bf16 hi/lo) in m16n8k16 order
    const int w    = tid >> 5;
    const int lane = tid & 31;
    const int g = lane >> 2, t = lane & 3;
    const int er = w * 16 + g;

#pragma unroll
    for (int kt = 0; kt < 4; ++kt) {
        const int k0 = kt * 16 + 2 * t;
        const float* b0 = sHa + (k0)     * HT;
        const float* b1 = sHa + (k0 + 1) * HT;
        const float* b8 = sHa + (k0 + 8) * HT;
        const float* b9 = sHa + (k0 + 9) * HT;
        uint4 vh, vl;
        split_pack(b0[er],     b1[er],     vh.x, vl.x);
        split_pack(b0[er + 8], b1[er + 8], vh.y, vl.y);
        split_pack(b8[er],     b9[er],     vh.z, vl.z);
        split_pack(b8[er + 8], b9[er + 8], vh.w, vl.w);
        const int idx = ((blockIdx.x * 8 + w) * 4 + kt) * 32 + lane;
        g_ah4[idx] = vh;
        g_al4[idx] = vl;
    }
}

// ---------------------------------------------------------------------------
// Kernel 2: zero the aggregation buffer (float4)
// ---------------------------------------------------------------------------
__global__ void __launch_bounds__(256)
zero_kernel()
{
    const size_t i = (size_t)blockIdx.x * 256 + threadIdx.x;
    ((float4*)g_agg)[i] = make_float4(0.f, 0.f, 0.f, 0.f);
}

// ---------------------------------------------------------------------------
// Kernel 3: FUSED GEMM4 + tensor-product messages + scatter.
// 128 edges per block, 8 warps x 16 edges. Per 8-column tile, each warp
// accumulates the 5 radial chunks via HMMA, shuffle-redistributes fragments
// so each lane owns (1 edge x 4 contiguous channels), computes messages,
// and issues red.global.add.v4 directly. No g_w materialization.
// ---------------------------------------------------------------------------
__global__ void __launch_bounds__(256, 2)
fused_kernel(const float* __restrict__ nf, const float* __restrict__ ef,
             const float* __restrict__ attrs,
             const int* __restrict__ snd, const int* __restrict__ rcv)
{
    const int tid  = threadIdx.x;
    const int w    = tid >> 5;
    const int lane = tid & 31;
    const int gr   = lane >> 2;
    const int t    = lane & 3;
    const size_t e0 = (size_t)blockIdx.x * 128;

    // this lane's message edge (fixed across tiles)
    const size_t em = e0 + (size_t)(w * 16 + gr + 8 * (t & 1));
    const int s = snd[em], r = rcv[em];
    const float4 sh = *(const float4*)(attrs + em * 4);
    const float sh0 = sh.x, s1x = sh.y, s1y = sh.z, s1z = sh.w;
    const float* ps = nf + (size_t)s * DD;
    const float* pr = nf + (size_t)r * DD;
    const float* pe = ef + em * DD;
    float* pagg = g_agg + (size_t)r * DD;

    // load resident A fragments
    uint32_t Ah[4][4], Al[4][4];
#pragma unroll
    for (int kt = 0; kt < 4; ++kt) {
        const int idx = ((blockIdx.x * 8 + w) * 4 + kt) * 32 + lane;
        const uint4 vh = g_ah4[idx];
        const uint4 vl = g_al4[idx];
        Ah[kt][0] = vh.x; Ah[kt][1] = vh.y; Ah[kt][2] = vh.z; Ah[kt][3] = vh.w;
        Al[kt][0] = vl.x; Al[kt][1] = vl.y; Al[kt][2] = vl.z; Al[kt][3] = vl.w;
    }

#pragma unroll 1
    for (int tile = 0; tile < 16; ++tile) {
        float acc[5][4];
#pragma unroll
        for (int q = 0; q < 5; ++q)
#pragma unroll
            for (int i = 0; i < 4; ++i) acc[q][i] = 0.f;

#pragma unroll
        for (int q = 0; q < 5; ++q) {
#pragma unroll
            for (int kt = 0; kt < 4; ++kt) {
                const int idx = ((kt * 80 + q * 16 + tile) * 32 + lane) * 2;
                const uint2 bh = __ldg((const uint2*)(g_b4h + idx));
                const uint2 bl = __ldg((const uint2*)(g_b4l + idx));
                mma_bf16(acc[q], Ah[kt], bh.x, bh.y);
                mma_bf16(acc[q], Al[kt], bh.x, bh.y);
                mma_bf16(acc[q], Ah[kt], bl.x, bl.y);
            }
        }

        // redistribute: lane -> (edge em, channels cm..cm+3)
        // t even holds (gr) pair in acc[0..1]; sends its (gr+8) pair acc[2..3].
        // t odd holds (gr+8) pair in acc[2..3]; sends its (gr) pair acc[0..1].
#pragma unroll
        for (int q = 0; q < 5; ++q) {
            const float s0 = (t & 1) ? acc[q][0] : acc[q][2];
            const float s1 = (t & 1) ? acc[q][1] : acc[q][3];
            const float r0 = __shfl_xor_sync(0xffffffffu, s0, 1);
            const float r1 = __shfl_xor_sync(0xffffffffu, s1, 1);
            if (t & 1) { acc[q][0] = r0; acc[q][1] = r1; }
            else       { acc[q][2] = r0; acc[q][3] = r1; }
        }
        const int cm = tile * 8 + (t >> 1) * 4;

        // gather x features for (em, cm..cm+3)
        float x0[4], xv[12];
        {
            const float4 a = __ldg((const float4*)(ps + cm));
            const float4 b = __ldg((const float4*)(pr + cm));
            const float4 c = __ldg((const float4*)(pe + cm));
            x0[0] = a.x + b.x + c.x; x0[1] = a.y + b.y + c.y;
            x0[2] = a.z + b.z + c.z; x0[3] = a.w + b.w + c.w;
        }
#pragma unroll
        for (int sp = 0; sp < 3; ++sp) {
            const int off = CC + 3 * cm + 4 * sp;
            const float4 a = __ldg((const float4*)(ps + off));
            const float4 b = __ldg((const float4*)(pr + off));
            const float4 c = __ldg((const float4*)(pe + off));
            xv[4 * sp + 0] = a.x + b.x + c.x; xv[4 * sp + 1] = a.y + b.y + c.y;
            xv[4 * sp + 2] = a.z + b.z + c.z; xv[4 * sp + 3] = a.w + b.w + c.w;
        }

        float m0v[4], m1v[12];
#pragma unroll
        for (int j = 0; j < 4; ++j) {
            const float u0 = xv[3 * j], u1 = xv[3 * j + 1], u2 = xv[3 * j + 2];
            const float dot = u0 * s1x + u1 * s1y + u2 * s1z;
            m0v[j] = acc[0][j] * x0[j] * sh0 + acc[1][j] * dot * INV_SQRT3;
            const float cx = u1 * s1z - u2 * s1y;
            const float cy = u2 * s1x - u0 * s1z;
            const float cz = u0 * s1y - u1 * s1x;
            m1v[3 * j + 0] = acc[2][j] * u0 * sh0 + acc[3][j] * x0[j] * s1x + acc[4][j] * cx * INV_SQRT2;
            m1v[3 * j + 1] = acc[2][j] * u1 * sh0 + acc[3][j] * x0[j] * s1y + acc[4][j] * cy * INV_SQRT2;
            m1v[3 * j + 2] = acc[2][j] * u2 * sh0 + acc[3][j] * x0[j] * s1z + acc[4][j] * cz * INV_SQRT2;
        }

        asm volatile("red.global.add.v4.f32 [%0], {%1,%2,%3,%4};"
                     :: "l"(pagg + cm), "f"(m0v[0]), "f"(m0v[1]), "f"(m0v[2]), "f"(m0v[3])
                     : "memory");
        float* pv = pagg + CC + 3 * cm;
        asm volatile("red.global.add.v4.f32 [%0], {%1,%2,%3,%4};"
                     :: "l"(pv), "f"(m1v[0]), "f"(m1v[1]), "f"(m1v[2]), "f"(m1v[3])
                     : "memory");
        asm volatile("red.global.add.v4.f32 [%0], {%1,%2,%3,%4};"
                     :: "l"(pv + 4), "f"(m1v[4]), "f"(m1v[5]), "f"(m1v[6]), "f"(m1v[7])
                     : "memory");
        asm volatile("red.global.add.v4.f32 [%0], {%1,%2,%3,%4};"
                     :: "l"(pv + 8), "f"(m1v[8]), "f"(m1v[9]), "f"(m1v[10]), "f"(m1v[11])
                     : "memory");
    }
}

// ---------------------------------------------------------------------------
// Kernel 4: out = agg + eq_linear(agg,res) + eq_linear(nf,skip).
// ---------------------------------------------------------------------------
#define OST 18
#define OARR (CC * OST)

__global__ void __launch_bounds__(256, 2)
out_kernel(const float* __restrict__ nf,
           const float* __restrict__ rW0, const float* __restrict__ rW1,
           const float* __restrict__ skW0, const float* __restrict__ skW1,
           float* __restrict__ out)
{
    extern __shared__ float osm[];
    float* sA0 = osm;
    float* sN0 = osm + 4 * OARR;

    const int tid = threadIdx.x;
    const size_t n0 = (size_t)blockIdx.x * 16;

    for (int i = tid; i < 16 * DD; i += 256) {
        const int n = i >> 9;
        const int q = i & 511;
        const float va = g_agg[(n0 + n) * DD + q];
        const float vb = nf[(n0 + n) * DD + q];
        if (q < CC) {
            sA0[q * OST + n] = va;
            sN0[q * OST + n] = vb;
        } else {
            const int rr = q - CC;
            const int c = rr / 3;
            const int ax = rr - 3 * c;
            sA0[(1 + ax) * OARR + c * OST + n] = va;
            sN0[(1 + ax) * OARR + c * OST + n] = vb;
        }
    }
    __syncthreads();

    const int dg = tid & 31;
    const int ng = tid >> 5;
    const int d0 = dg * 4;
    const int nn2 = ng * 2;

    u64 acc0[4], accx[4], accy[4], accz[4];
#pragma unroll
    for (int d = 0; d < 4; ++d) { acc0[d] = 0ull; accx[d] = 0ull; accy[d] = 0ull; accz[d] = 0ull; }

#pragma unroll 4
    for (int c = 0; c < CC; ++c) {
        const float4 wr0 = __ldg((const float4*)(rW0  + c * CC + d0));
        const float4 ws0 = __ldg((const float4*)(skW0 + c * CC + d0));
        const float4 wr1 = __ldg((const float4*)(rW1  + c * CC + d0));
        const float4 ws1 = __ldg((const float4*)(skW1 + c * CC + d0));
        const int ab = c * OST + nn2;
        const u64 pA0 = *(const u64*)(sA0 + ab);
        const u64 pAx = *(const u64*)(sA0 + OARR + ab);
        const u64 pAy = *(const u64*)(sA0 + 2 * OARR + ab);
        const u64 pAz = *(const u64*)(sA0 + 3 * OARR + ab);
        const u64 pN0 = *(const u64*)(sN0 + ab);
        const u64 pNx = *(const u64*)(sN0 + OARR + ab);
        const u64 pNy = *(const u64*)(sN0 + 2 * OARR + ab);
        const u64 pNz = *(const u64*)(sN0 + 3 * OARR + ab);

        const float r0a[4] = {wr0.x, wr0.y, wr0.z, wr0.w};
        const float s0a[4] = {ws0.x, ws0.y, ws0.z, ws0.w};
        const float r1a[4] = {wr1.x, wr1.y, wr1.z, wr1.w};
        const float s1a[4] = {ws1.x, ws1.y, ws1.z, ws1.w};
#pragma unroll
        for (int d = 0; d < 4; ++d) {
            const u64 pr0 = pack2(r0a[d], r0a[d]);
            const u64 ps0 = pack2(s0a[d], s0a[d]);
            const u64 pr1 = pack2(r1a[d], r1a[d]);
            const u64 ps1 = pack2(s1a[d], s1a[d]);
            fma2(acc0[d], pA0, pr0); fma2(acc0[d], pN0, ps0);
            fma2(accx[d], pAx, pr1); fma2(accx[d], pNx, ps1);
            fma2(accy[d], pAy, pr1); fma2(accy[d], pNy, ps1);
            fma2(accz[d], pAz, pr1); fma2(accz[d], pNz, ps1);
        }
    }

#pragma unroll
    for (int s = 0; s < 2; ++s) {
        const int n = nn2 + s;
        const size_t ob = (n0 + n) * DD;
        float o4[4], vv[12];
#pragma unroll
        for (int d = 0; d < 4; ++d) {
            float lo, hi, v;
            unpack2(acc0[d], lo, hi); v = s ? hi : lo;
            o4[d] = sA0[(d0 + d) * OST + n] + v * LIN_SCALE;
            unpack2(accx[d], lo, hi); v = s ? hi : lo;
            vv[3 * d + 0] = sA0[OARR + (d0 + d) * OST + n] + v * LIN_SCALE;
            unpack2(accy[d], lo, hi); v = s ? hi : lo;
            vv[3 * d + 1] = sA0[2 * OARR + (d0 + d) * OST + n] + v * LIN_SCALE;
            unpack2(accz[d], lo, hi); v = s ? hi : lo;
            vv[3 * d + 2] = sA0[3 * OARR + (d0 + d) * OST + n] + v * LIN_SCALE;
        }
        *(float4*)(out + ob + d0) = make_float4(o4[0], o4[1], o4[2], o4[3]);
        float* vb = out + ob + CC + 3 * d0;
        *(float4*)(vb    ) = make_float4(vv[0], vv[1], vv[2],  vv[3]);
        *(float4*)(vb + 4) = make_float4(vv[4], vv[5], vv[6],  vv[7]);
        *(float4*)(vb + 8) = make_float4(vv[8], vv[9], vv[10], vv[11]);
    }
}

// ---------------------------------------------------------------------------
extern "C" void kernel_launch(void* const* d_in, const int* in_sizes, int n_in,
                              void* d_out, int out_size)
{
    const float* nf    = (const float*)d_in[0];
    const float* ef    = (const float*)d_in[1];
    const float* attrs = (const float*)d_in[2];
    const float* emb   = (const float*)d_in[3];
    const int*   snd   = (const int*)d_in[4];
    const int*   rcv   = (const int*)d_in[5];
    const float* Wm1   = (const float*)d_in[6];
    const float* Wm2   = (const float*)d_in[7];
    const float* Wm3   = (const float*)d_in[8];
    const float* Wm4   = (const float*)d_in[9];
    const float* rW0   = (const float*)d_in[10];
    const float* rW1   = (const float*)d_in[11];
    const float* sW0   = (const float*)d_in[12];
    const float* sW1   = (const float*)d_in[13];
    float* out = (float*)d_out;

    const int mlp_smem = (1536 + 2 * HH * HT) * 4;   // 72704 B
    const int out_smem = 8 * OARR * 4;               // 73728 B
    static bool attr_done = false;
    if (!attr_done) {
        cudaFuncSetAttribute(mlp_kernel, cudaFuncAttributeMaxDynamicSharedMemorySize, mlp_smem);
        cudaFuncSetAttribute(out_kernel, cudaFuncAttributeMaxDynamicSharedMemorySize, out_smem);
        attr_done = true;
    }

    zero_kernel<<<(NN * DD) / (256 * 4), 256>>>();
    prep_b4_kernel<<<(4 * 80 * 32 + 255) / 256, 256>>>(Wm4);
    mlp_kernel<<<EE / 128, 256, mlp_smem>>>(emb, Wm1, Wm2, Wm3);
    fused_kernel<<<EE / 128, 256>>>(nf, ef, attrs, snd, rcv);
    out_kernel<<<NN / 16, 256, out_smem>>>(nf, rW0, rW1, sW0, sW1, out);
}

// round 7
// speedup vs baseline: 1.9956x; 1.0099x over previous
#include <cuda_runtime.h>
#include <cuda_bf16.h>
#include <cstdint>

#define NN 10000
#define EE 160000
#define CC 128
#define DD 512
#define HH 64
#define W4C 640
#define HT 130   // padded stride for transposed h tiles [k][e]

#define INV_SQRT3 0.57735026918962576f
#define INV_SQRT2 0.70710678118654752f
#define LIN_SCALE 0.088388347648318447f   // 1/sqrt(128)

// Scratch (device globals: no runtime allocation allowed)
__device__ float g_agg[(size_t)NN * DD];          // segment-sum accumulator
// A fragments (layer-3 activations), bf16 hi/lo, m16n8k16 A-fragment order:
// uint4 per [blk(1250)][warp(8)][kt(4)][lane(32)]
__device__ uint4 g_ah4[1250 * 8 * 4 * 32];
__device__ uint4 g_al4[1250 * 8 * 4 * 32];
// Wm4 split bf16, B-fragment order, hi+lo packed: uint4{h0,h1,l0,l1}
// per [kt(4)][nt(80)][lane(32)]
__device__ uint4 g_b4[4 * 80 * 32];

typedef unsigned long long u64;

__device__ __forceinline__ u64 pack2(float lo, float hi) {
    u64 r; asm("mov.b64 %0, {%1, %2};" : "=l"(r) : "f"(lo), "f"(hi)); return r;
}
__device__ __forceinline__ void unpack2(u64 v, float& lo, float& hi) {
    asm("mov.b64 {%0, %1}, %2;" : "=f"(lo), "=f"(hi) : "l"(v));
}
__device__ __forceinline__ void fma2(u64& d, u64 a, u64 b) {
    asm("fma.rn.f32x2 %0, %1, %2, %0;" : "+l"(d) : "l"(a), "l"(b));
}
__device__ __forceinline__ float silu_f(float x) { return x / (1.0f + __expf(-x)); }

__device__ __forceinline__ uint32_t pack_bf16(__nv_bfloat16 first, __nv_bfloat16 second) {
    return (uint32_t)__bfloat16_as_ushort(first) | ((uint32_t)__bfloat16_as_ushort(second) << 16);
}
__device__ __forceinline__ void split_pack(float x, float y, uint32_t& hi, uint32_t& lo) {
    const __nv_bfloat16 bx = __float2bfloat16(x);
    const __nv_bfloat16 by = __float2bfloat16(y);
    const __nv_bfloat16 rx = __float2bfloat16(x - __bfloat162float(bx));
    const __nv_bfloat16 ry = __float2bfloat16(y - __bfloat162float(by));
    hi = pack_bf16(bx, by);
    lo = pack_bf16(rx, ry);
}

__device__ __forceinline__ void mma_bf16(float* c, const uint32_t* a, uint32_t b0, uint32_t b1) {
    asm volatile("mma.sync.aligned.m16n8k16.row.col.f32.bf16.bf16.f32 "
        "{%0,%1,%2,%3}, {%4,%5,%6,%7}, {%8,%9}, {%0,%1,%2,%3};"
        : "+f"(c[0]), "+f"(c[1]), "+f"(c[2]), "+f"(c[3])
        : "r"(a[0]), "r"(a[1]), "r"(a[2]), "r"(a[3]), "r"(b0), "r"(b1));
}

// ---------------------------------------------------------------------------
// prep: split Wm4 -> bf16 hi/lo in B-fragment order, hi+lo packed per uint4.
// ---------------------------------------------------------------------------
__global__ void __launch_bounds__(256)
prep_b4_kernel(const float* __restrict__ Wm4)
{
    const int tid = blockIdx.x * 256 + threadIdx.x;
    if (tid >= 4 * 80 * 32) return;
    const int lane = tid & 31;
    const int idx = tid >> 5;           // kt*80 + nt
    const int kt = idx / 80, nt = idx % 80;
    const int g = lane >> 2, t = lane & 3;
    const int n = nt * 8 + g;
    const int k0 = kt * 16 + 2 * t;

    const float v00 = Wm4[(k0)     * W4C + n];
    const float v01 = Wm4[(k0 + 1) * W4C + n];
    const float v10 = Wm4[(k0 + 8) * W4C + n];
    const float v11 = Wm4[(k0 + 9) * W4C + n];
    uint4 o;
    split_pack(v00, v01, o.x, o.z);
    split_pack(v10, v11, o.y, o.w);
    g_b4[idx * 32 + lane] = o;
}

// ---------------------------------------------------------------------------
// One 64->64 layer, register-blocked: 4 columns x 8 edges per thread.
// ---------------------------------------------------------------------------
__device__ __forceinline__ void layer_rb(const float* __restrict__ W,
                                         const float* sIn, float* sOut,
                                         int jbase, int ebase)
{
    u64 acc[4][4];
#pragma unroll
    for (int c = 0; c < 4; ++c)
#pragma unroll
        for (int p = 0; p < 4; ++p) acc[c][p] = 0ull;

#pragma unroll 4
    for (int k = 0; k < HH; ++k) {
        const float4 w4 = __ldg((const float4*)(W + k * HH + jbase));
        const u64* hp = (const u64*)(sIn + k * HT + ebase);
        const u64 h0 = hp[0], h1 = hp[1], h2 = hp[2], h3 = hp[3];
        const float wv[4] = {w4.x, w4.y, w4.z, w4.w};
#pragma unroll
        for (int c = 0; c < 4; ++c) {
            const u64 w2 = pack2(wv[c], wv[c]);
            fma2(acc[c][0], h0, w2);
            fma2(acc[c][1], h1, w2);
            fma2(acc[c][2], h2, w2);
            fma2(acc[c][3], h3, w2);
        }
    }
#pragma unroll
    for (int c = 0; c < 4; ++c) {
        u64* op = (u64*)(sOut + (jbase + c) * HT + ebase);
#pragma unroll
        for (int p = 0; p < 4; ++p) {
            float lo, hi; unpack2(acc[c][p], lo, hi);
            op[p] = pack2(silu_f(lo), silu_f(hi));
        }
    }
}

// ---------------------------------------------------------------------------
// Kernel 1: MLP layers 1-3 (scalar) -> store split bf16 A-fragments.
// ---------------------------------------------------------------------------
__global__ void __launch_bounds__(256, 2)
mlp_kernel(const float* __restrict__ emb, const float* __restrict__ Wm1,
           const float* __restrict__ Wm2, const float* __restrict__ Wm3)
{
    extern __shared__ float sm[];
    float* sE  = sm;            // 128 x 8
    float* sW1 = sm + 1024;     // 8 x 64
    float* sHa = sm + 1536;     // [64][130]
    float* sHb = sm + 1536 + HH * HT;

    const int tid = threadIdx.x;
    const size_t e0 = (size_t)blockIdx.x * 128;

    for (int i = tid; i < 1024; i += 256) sE[i] = emb[e0 * 8 + i];
    for (int i = tid; i < 512; i += 256)  sW1[i] = Wm1[i];
    __syncthreads();

    const int jq = tid & 15;
    const int eg = tid >> 4;
    const int jbase = jq * 4;
    const int ebase = eg * 8;

    // layer 1
    {
        float w[8][4];
#pragma unroll
        for (int r = 0; r < 8; ++r) {
            const float4 w4 = *(const float4*)(sW1 + r * HH + jbase);
            w[r][0] = w4.x; w[r][1] = w4.y; w[r][2] = w4.z; w[r][3] = w4.w;
        }
#pragma unroll
        for (int e = 0; e < 8; ++e) {
            const float4 ea = *(const float4*)(sE + (ebase + e) * 8);
            const float4 eb = *(const float4*)(sE + (ebase + e) * 8 + 4);
            const float er[8] = {ea.x, ea.y, ea.z, ea.w, eb.x, eb.y, eb.z, eb.w};
#pragma unroll
            for (int c = 0; c < 4; ++c) {
                float acc = 0.f;
#pragma unroll
                for (int r = 0; r < 8; ++r) acc += er[r] * w[r][c];
                sHa[(jbase + c) * HT + ebase + e] = silu_f(acc);
            }
        }
    }
    __syncthreads();
    layer_rb(Wm2, sHa, sHb, jbase, ebase);
    __syncthreads();
    layer_rb(Wm3, sHb, sHa, jbase, ebase);
    __syncthreads();

    // build + store A fragments (bf16 hi/lo) in m16n8k16 order
    const int w    = tid >> 5;
    const int lane = tid & 31;
    const int g = lane >> 2, t = lane & 3;
    const int er = w * 16 + g;

#pragma unroll
    for (int kt = 0; kt < 4; ++kt) {
        const int k0 = kt * 16 + 2 * t;
        const float* b0 = sHa + (k0)     * HT;
        const float* b1 = sHa + (k0 + 1) * HT;
        const float* b8 = sHa + (k0 + 8) * HT;
        const float* b9 = sHa + (k0 + 9) * HT;
        uint4 vh, vl;
        split_pack(b0[er],     b1[er],     vh.x, vl.x);
        split_pack(b0[er + 8], b1[er + 8], vh.y, vl.y);
        split_pack(b8[er],     b9[er],     vh.z, vl.z);
        split_pack(b8[er + 8], b9[er + 8], vh.w, vl.w);
        const int idx = ((blockIdx.x * 8 + w) * 4 + kt) * 32 + lane;
        g_ah4[idx] = vh;
        g_al4[idx] = vl;
    }
}

// ---------------------------------------------------------------------------
// Kernel 2: zero the aggregation buffer (float4)
// ---------------------------------------------------------------------------
__global__ void __launch_bounds__(256)
zero_kernel()
{
    const size_t i = (size_t)blockIdx.x * 256 + threadIdx.x;
    ((float4*)g_agg)[i] = make_float4(0.f, 0.f, 0.f, 0.f);
}

// ---------------------------------------------------------------------------
// Kernel 3: FUSED GEMM4 + tensor-product messages + scatter, with coalesced
// smem staging of x features. Per warp: 16 edges; per tile: 8 lanes per edge
// cooperatively load (ps+pr+pe) pieces and write each float4 directly into
// the consumer lane's padded smem slot.
// ---------------------------------------------------------------------------
__global__ void __launch_bounds__(256, 2)
fused_kernel(const float* __restrict__ nf, const float* __restrict__ ef,
             const float* __restrict__ attrs,
             const int* __restrict__ snd, const int* __restrict__ rcv)
{
    __shared__ int    s_snd[8][16];
    __shared__ int    s_rcv[8][16];
    __shared__ float4 s_y[8][32 * 5];   // per warp: 32 consumer lanes x 5 slots (pad)

    const int tid  = threadIdx.x;
    const int w    = tid >> 5;
    const int lane = tid & 31;
    const int gr   = lane >> 2;
    const int t    = lane & 3;
    const size_t e0 = (size_t)blockIdx.x * 128;

    if (lane < 16) {
        s_snd[w][lane] = snd[e0 + (size_t)(w * 16 + lane)];
        s_rcv[w][lane] = rcv[e0 + (size_t)(w * 16 + lane)];
    }
    __syncwarp();

    // this lane's message edge (fixed across tiles)
    const int eml = gr + 8 * (t & 1);
    const size_t em = e0 + (size_t)(w * 16 + eml);
    const float4 sh = *(const float4*)(attrs + em * 4);
    const float sh0 = sh.x, s1x = sh.y, s1y = sh.z, s1z = sh.w;
    float* pagg = g_agg + (size_t)s_rcv[w][eml] * DD;

    // producer-role constants: this lane stages float4 piece jP of 4 edges
    const int jP = lane & 7;
    const int ch4P  = (jP < 2) ? jP : (jP - 2) / 3;
    const int slotP = (jP < 2) ? 0 : ((jP - 2) % 3) + 1;
    const int offMul = (jP < 2) ? 8 : 24;
    const int offAdd = (jP < 2) ? jP * 4 : CC + (jP - 2) * 4;
    const int elBase = lane >> 3;       // + 4*it

    // load resident A fragments
    uint32_t Ah[4][4], Al[4][4];
#pragma unroll
    for (int kt = 0; kt < 4; ++kt) {
        const int idx = ((blockIdx.x * 8 + w) * 4 + kt) * 32 + lane;
        const uint4 vh = g_ah4[idx];
        const uint4 vl = g_al4[idx];
        Ah[kt][0] = vh.x; Ah[kt][1] = vh.y; Ah[kt][2] = vh.z; Ah[kt][3] = vh.w;
        Al[kt][0] = vl.x; Al[kt][1] = vl.y; Al[kt][2] = vl.z; Al[kt][3] = vl.w;
    }

#pragma unroll 1
    for (int tile = 0; tile < 16; ++tile) {
        // 1) issue staging loads first (latency hidden under HMMA below)
        const int off = tile * offMul + offAdd;
        float4 xa[4], xb[4], xc[4];
#pragma unroll
        for (int it = 0; it < 4; ++it) {
            const int el = it * 4 + elBase;
            xa[it] = __ldg((const float4*)(nf + (size_t)s_snd[w][el] * DD + off));
            xb[it] = __ldg((const float4*)(nf + (size_t)s_rcv[w][el] * DD + off));
            xc[it] = __ldg((const float4*)(ef + (e0 + (size_t)(w * 16 + el)) * DD + off));
        }

        // 2) HMMA: 5 radial chunks, 3-term bf16 split
        float acc[5][4];
#pragma unroll
        for (int q = 0; q < 5; ++q)
#pragma unroll
            for (int i = 0; i < 4; ++i) acc[q][i] = 0.f;

#pragma unroll
        for (int q = 0; q < 5; ++q) {
#pragma unroll
            for (int kt = 0; kt < 4; ++kt) {
                const uint4 bb = __ldg(g_b4 + ((kt * 80 + q * 16 + tile) * 32 + lane));
                mma_bf16(acc[q], Ah[kt], bb.x, bb.y);
                mma_bf16(acc[q], Al[kt], bb.x, bb.y);
                mma_bf16(acc[q], Ah[kt], bb.z, bb.w);
            }
        }

        // 3) sum + store into consumer slots
#pragma unroll
        for (int it = 0; it < 4; ++it) {
            const int el = it * 4 + elBase;
            const int c = (el & 7) * 4 + (el >> 3) + 2 * ch4P;
            s_y[w][c * 5 + slotP] = make_float4(
                xa[it].x + xb[it].x + xc[it].x,
                xa[it].y + xb[it].y + xc[it].y,
                xa[it].z + xb[it].z + xc[it].z,
                xa[it].w + xb[it].w + xc[it].w);
        }
        __syncwarp();

        // 4) read own x pieces
        const float4* my = &s_y[w][lane * 5];
        const float4 X0 = my[0];
        const float4 V0 = my[1];
        const float4 V1 = my[2];
        const float4 V2 = my[3];
        const float x0[4]  = {X0.x, X0.y, X0.z, X0.w};
        const float xv[12] = {V0.x, V0.y, V0.z, V0.w,
                              V1.x, V1.y, V1.z, V1.w,
                              V2.x, V2.y, V2.z, V2.w};

        // 5) redistribute HMMA fragments: lane -> (edge em, channels cm..cm+3)
#pragma unroll
        for (int q = 0; q < 5; ++q) {
            const float s0 = (t & 1) ? acc[q][0] : acc[q][2];
            const float s1 = (t & 1) ? acc[q][1] : acc[q][3];
            const float r0 = __shfl_xor_sync(0xffffffffu, s0, 1);
            const float r1 = __shfl_xor_sync(0xffffffffu, s1, 1);
            if (t & 1) { acc[q][0] = r0; acc[q][1] = r1; }
            else       { acc[q][2] = r0; acc[q][3] = r1; }
        }
        const int cm = tile * 8 + (t >> 1) * 4;

        // 6) messages
        float m0v[4], m1v[12];
#pragma unroll
        for (int j = 0; j < 4; ++j) {
            const float u0 = xv[3 * j], u1 = xv[3 * j + 1], u2 = xv[3 * j + 2];
            const float dot = u0 * s1x + u1 * s1y + u2 * s1z;
            m0v[j] = acc[0][j] * x0[j] * sh0 + acc[1][j] * dot * INV_SQRT3;
            const float cx = u1 * s1z - u2 * s1y;
            const float cy = u2 * s1x - u0 * s1z;
            const float cz = u0 * s1y - u1 * s1x;
            m1v[3 * j + 0] = acc[2][j] * u0 * sh0 + acc[3][j] * x0[j] * s1x + acc[4][j] * cx * INV_SQRT2;
            m1v[3 * j + 1] = acc[2][j] * u1 * sh0 + acc[3][j] * x0[j] * s1y + acc[4][j] * cy * INV_SQRT2;
            m1v[3 * j + 2] = acc[2][j] * u2 * sh0 + acc[3][j] * x0[j] * s1z + acc[4][j] * cz * INV_SQRT2;
        }

        asm volatile("red.global.add.v4.f32 [%0], {%1,%2,%3,%4};"
                     :: "l"(pagg + cm), "f"(m0v[0]), "f"(m0v[1]), "f"(m0v[2]), "f"(m0v[3])
                     : "memory");
        float* pv = pagg + CC + 3 * cm;
        asm volatile("red.global.add.v4.f32 [%0], {%1,%2,%3,%4};"
                     :: "l"(pv), "f"(m1v[0]), "f"(m1v[1]), "f"(m1v[2]), "f"(m1v[3])
                     : "memory");
        asm volatile("red.global.add.v4.f32 [%0], {%1,%2,%3,%4};"
                     :: "l"(pv + 4), "f"(m1v[4]), "f"(m1v[5]), "f"(m1v[6]), "f"(m1v[7])
                     : "memory");
        asm volatile("red.global.add.v4.f32 [%0], {%1,%2,%3,%4};"
                     :: "l"(pv + 8), "f"(m1v[8]), "f"(m1v[9]), "f"(m1v[10]), "f"(m1v[11])
                     : "memory");
        __syncwarp();
    }
}

// ---------------------------------------------------------------------------
// Kernel 4: out = agg + eq_linear(agg,res) + eq_linear(nf,skip).
// ---------------------------------------------------------------------------
#define OST 18
#define OARR (CC * OST)

__global__ void __launch_bounds__(256, 2)
out_kernel(const float* __restrict__ nf,
           const float* __restrict__ rW0, const float* __restrict__ rW1,
           const float* __restrict__ skW0, const float* __restrict__ skW1,
           float* __restrict__ out)
{
    extern __shared__ float osm[];
    float* sA0 = osm;
    float* sN0 = osm + 4 * OARR;

    const int tid = threadIdx.x;
    const size_t n0 = (size_t)blockIdx.x * 16;

    for (int i = tid; i < 16 * DD; i += 256) {
        const int n = i >> 9;
        const int q = i & 511;
        const float va = g_agg[(n0 + n) * DD + q];
        const float vb = nf[(n0 + n) * DD + q];
        if (q < CC) {
            sA0[q * OST + n] = va;
            sN0[q * OST + n] = vb;
        } else {
            const int rr = q - CC;
            const int c = rr / 3;
            const int ax = rr - 3 * c;
            sA0[(1 + ax) * OARR + c * OST + n] = va;
            sN0[(1 + ax) * OARR + c * OST + n] = vb;
        }
    }
    __syncthreads();

    const int dg = tid & 31;
    const int ng = tid >> 5;
    const int d0 = dg * 4;
    const int nn2 = ng * 2;

    u64 acc0[4], accx[4], accy[4], accz[4];
#pragma unroll
    for (int d = 0; d < 4; ++d) { acc0[d] = 0ull; accx[d] = 0ull; accy[d] = 0ull; accz[d] = 0ull; }

#pragma unroll 4
    for (int c = 0; c < CC; ++c) {
        const float4 wr0 = __ldg((const float4*)(rW0  + c * CC + d0));
        const float4 ws0 = __ldg((const float4*)(skW0 + c * CC + d0));
        const float4 wr1 = __ldg((const float4*)(rW1  + c * CC + d0));
        const float4 ws1 = __ldg((const float4*)(skW1 + c * CC + d0));
        const int ab = c * OST + nn2;
        const u64 pA0 = *(const u64*)(sA0 + ab);
        const u64 pAx = *(const u64*)(sA0 + OARR + ab);
        const u64 pAy = *(const u64*)(sA0 + 2 * OARR + ab);
        const u64 pAz = *(const u64*)(sA0 + 3 * OARR + ab);
        const u64 pN0 = *(const u64*)(sN0 + ab);
        const u64 pNx = *(const u64*)(sN0 + OARR + ab);
        const u64 pNy = *(const u64*)(sN0 + 2 * OARR + ab);
        const u64 pNz = *(const u64*)(sN0 + 3 * OARR + ab);

        const float r0a[4] = {wr0.x, wr0.y, wr0.z, wr0.w};
        const float s0a[4] = {ws0.x, ws0.y, ws0.z, ws0.w};
        const float r1a[4] = {wr1.x, wr1.y, wr1.z, wr1.w};
        const float s1a[4] = {ws1.x, ws1.y, ws1.z, ws1.w};
#pragma unroll
        for (int d = 0; d < 4; ++d) {
            const u64 pr0 = pack2(r0a[d], r0a[d]);
            const u64 ps0 = pack2(s0a[d], s0a[d]);
            const u64 pr1 = pack2(r1a[d], r1a[d]);
            const u64 ps1 = pack2(s1a[d], s1a[d]);
            fma2(acc0[d], pA0, pr0); fma2(acc0[d], pN0, ps0);
            fma2(accx[d], pAx, pr1); fma2(accx[d], pNx, ps1);
            fma2(accy[d], pAy, pr1); fma2(accy[d], pNy, ps1);
            fma2(accz[d], pAz, pr1); fma2(accz[d], pNz, ps1);
        }
    }

#pragma unroll
    for (int s = 0; s < 2; ++s) {
        const int n = nn2 + s;
        const size_t ob = (n0 + n) * DD;
        float o4[4], vv[12];
#pragma unroll
        for (int d = 0; d < 4; ++d) {
            float lo, hi, v;
            unpack2(acc0[d], lo, hi); v = s ? hi : lo;
            o4[d] = sA0[(d0 + d) * OST + n] + v * LIN_SCALE;
            unpack2(accx[d], lo, hi); v = s ? hi : lo;
            vv[3 * d + 0] = sA0[OARR + (d0 + d) * OST + n] + v * LIN_SCALE;
            unpack2(accy[d], lo, hi); v = s ? hi : lo;
            vv[3 * d + 1] = sA0[2 * OARR + (d0 + d) * OST + n] + v * LIN_SCALE;
            unpack2(accz[d], lo, hi); v = s ? hi : lo;
            vv[3 * d + 2] = sA0[3 * OARR + (d0 + d) * OST + n] + v * LIN_SCALE;
        }
        *(float4*)(out + ob + d0) = make_float4(o4[0], o4[1], o4[2], o4[3]);
        float* vb = out + ob + CC + 3 * d0;
        *(float4*)(vb    ) = make_float4(vv[0], vv[1], vv[2],  vv[3]);
        *(float4*)(vb + 4) = make_float4(vv[4], vv[5], vv[6],  vv[7]);
        *(float4*)(vb + 8) = make_float4(vv[8], vv[9], vv[10], vv[11]);
    }
}

// ---------------------------------------------------------------------------
extern "C" void kernel_launch(void* const* d_in, const int* in_sizes, int n_in,
                              void* d_out, int out_size)
{
    const float* nf    = (const float*)d_in[0];
    const float* ef    = (const float*)d_in[1];
    const float* attrs = (const float*)d_in[2];
    const float* emb   = (const float*)d_in[3];
    const int*   snd   = (const int*)d_in[4];
    const int*   rcv   = (const int*)d_in[5];
    const float* Wm1   = (const float*)d_in[6];
    const float* Wm2   = (const float*)d_in[7];
    const float* Wm3   = (const float*)d_in[8];
    const float* Wm4   = (const float*)d_in[9];
    const float* rW0   = (const float*)d_in[10];
    const float* rW1   = (const float*)d_in[11];
    const float* sW0   = (const float*)d_in[12];
    const float* sW1   = (const float*)d_in[13];
    float* out = (float*)d_out;

    const int mlp_smem = (1536 + 2 * HH * HT) * 4;   // 72704 B
    const int out_smem = 8 * OARR * 4;               // 73728 B
    static bool attr_done = false;
    if (!attr_done) {
        cudaFuncSetAttribute(mlp_kernel, cudaFuncAttributeMaxDynamicSharedMemorySize, mlp_smem);
        cudaFuncSetAttribute(out_kernel, cudaFuncAttributeMaxDynamicSharedMemorySize, out_smem);
        attr_done = true;
    }

    zero_kernel<<<(NN * DD) / (256 * 4), 256>>>();
    prep_b4_kernel<<<(4 * 80 * 32 + 255) / 256, 256>>>(Wm4);
    mlp_kernel<<<EE / 128, 256, mlp_smem>>>(emb, Wm1, Wm2, Wm3);
    fused_kernel<<<EE / 128, 256>>>(nf, ef, attrs, snd, rcv);
    out_kernel<<<NN / 16, 256, out_smem>>>(nf, rW0, rW1, sW0, sW1, out);
}